// round 15
// baseline (speedup 1.0000x reference)
#include <cuda_runtime.h>
#include <math.h>
#include <stdint.h>

#define PP 1024
#define LL 32
#define EE 512
#define DD 768
#define NLAY 6
#define FFD 3072
#define TT (PP*LL)

// ---------------- scratch ----------------
__device__ float g_emb[TT*EE];
__device__ float g_qkv[TT*3*EE];
__device__ float g_patch[PP*EE];
__device__ float g_patcho[PP*EE];
__device__ float g_h[PP*DD];
__device__ float g_hn[PP*DD];
__device__ float g_qkvt[PP*3*DD];
__device__ float g_scores[8*PP*PP];
__device__ float g_attnt[PP*DD];
__device__ float g_ff[PP*FFD];
__device__ float g_vt[DD*PP];
__device__ float g_split[4*PP*DD];

// ---------------- block reductions ----------------
__device__ __forceinline__ float blockSum(float v){
    __shared__ float sh[32];
    int lane = threadIdx.x & 31, wid = threadIdx.x >> 5, nw = blockDim.x >> 5;
    #pragma unroll
    for (int o = 16; o; o >>= 1) v += __shfl_xor_sync(0xffffffffu, v, o);
    if (lane == 0) sh[wid] = v;
    __syncthreads();
    float t = (lane < nw) ? sh[lane] : 0.f;
    #pragma unroll
    for (int o = 16; o; o >>= 1) t += __shfl_xor_sync(0xffffffffu, t, o);
    __syncthreads();
    return t;
}
__device__ __forceinline__ float blockMax(float v){
    __shared__ float sh[32];
    int lane = threadIdx.x & 31, wid = threadIdx.x >> 5, nw = blockDim.x >> 5;
    #pragma unroll
    for (int o = 16; o; o >>= 1) v = fmaxf(v, __shfl_xor_sync(0xffffffffu, v, o));
    if (lane == 0) sh[wid] = v;
    __syncthreads();
    float t = (lane < nw) ? sh[lane] : -1e30f;
    #pragma unroll
    for (int o = 16; o; o >>= 1) t = fmaxf(t, __shfl_xor_sync(0xffffffffu, t, o));
    __syncthreads();
    return t;
}

// ---------------- embedding + mask ----------------
__global__ void embed_kernel(const int* __restrict__ tokens, const int* __restrict__ lengths,
                             const float* __restrict__ bemb, const float* __restrict__ lpos,
                             float* __restrict__ out){
    int idx = blockIdx.x * blockDim.x + threadIdx.x;
    if (idx >= TT * EE) return;
    int e = idx & (EE - 1);
    int t = idx >> 9;
    int l = t & (LL - 1);
    int p = t >> 5;
    float v = 0.f;
    if (l < lengths[p]) {
        int tok = tokens[t];
        v = bemb[tok * EE + e] + lpos[l * EE + e];
    }
    out[idx] = v;
}

// ---------------- bf16 helpers ----------------
__device__ __forceinline__ uint32_t pack_bf16(float v0, float v1){
    uint32_t r; asm("cvt.rn.bf16x2.f32 %0, %1, %2;" : "=r"(r) : "f"(v1), "f"(v0)); return r;
}
__device__ __forceinline__ void split_pair(float v0, float v1, uint32_t &hi, uint32_t &lo){
    hi = pack_bf16(v0, v1);
    float h0 = __uint_as_float(hi << 16);
    float h1 = __uint_as_float(hi & 0xffff0000u);
    lo = pack_bf16(v0 - h0, v1 - h1);
}
__device__ __forceinline__ void mma_bf16_k16(float* c, const uint32_t* a, const uint32_t* b){
    asm("mma.sync.aligned.m16n8k16.row.col.f32.bf16.bf16.f32 "
        "{%0,%1,%2,%3}, {%4,%5,%6,%7}, {%8,%9}, {%0,%1,%2,%3};"
        : "+f"(c[0]), "+f"(c[1]), "+f"(c[2]), "+f"(c[3])
        : "r"(a[0]), "r"(a[1]), "r"(a[2]), "r"(a[3]), "r"(b[0]), "r"(b[1]));
}

// ---------------- split-bf16 GEMM (3 MMAs per k16), fragment-order smem ----------------
// C[M,N] = A[M,K] * B[N,K]^T (+epi). K % BK == 0.
// batch via blockIdx.z = zh*ksplit + zk.
// epi: 0 none, 1 bias, 2 bias+gelu(exact), 3 bias+residual,
//      4 bias + ALSO scatter V third transposed: res[(gn-2*DD)*PP + gm] = v for gn >= 2*DD
template<int BM, int BN, int BK, int WARPS_M, int WARPS_N, int MINB>
__global__ void __launch_bounds__(WARPS_M*WARPS_N*32, MINB)
gemmbf_kernel(const float* __restrict__ A, const float* __restrict__ B,
              const float* __restrict__ bias, float* __restrict__ res,
              float* __restrict__ C,
              int M, int N, int K,
              int lda, int ldb, int ldc,
              long long bA, long long bB, long long bC, int epi,
              int ksplit, long long aOff, long long bOff, long long cOff){
    constexpr int THREADS = WARPS_M * WARPS_N * 32;
    constexpr int KC = BK / 16;
    constexpr int SL = BK / 4;
    constexpr int WM = BM / WARPS_M, WN = BN / WARPS_N;
    constexpr int MT = WM / 16, NT = WN / 8;
    constexpr int NH = NT / 2;
    constexpr int MTILES = BM / 16, NTILES = BN / 8;
    constexpr int ASZ = KC * MTILES * 32 * 4;
    constexpr int BSZ = KC * NTILES * 32 * 2;
    constexpr int A4 = BM * SL / THREADS;
    constexpr int B4 = BN * SL / THREADS;

    __shared__ alignas(16) uint32_t sAh[2][ASZ];
    __shared__ alignas(16) uint32_t sAl[2][ASZ];
    __shared__ alignas(16) uint32_t sBh[2][BSZ];
    __shared__ alignas(16) uint32_t sBl[2][BSZ];

    const int tid = threadIdx.x;
    const int zh = blockIdx.z / ksplit, zk = blockIdx.z % ksplit;
    A += (long long)zh * bA + (long long)zk * aOff;
    B += (long long)zh * bB + (long long)zk * bOff;
    C += (long long)zh * bC + (long long)zk * cOff;
    const int m0 = blockIdx.y * BM, n0 = blockIdx.x * BN;
    const int w = tid >> 5, lane = tid & 31;
    const int g = lane >> 2, t4 = lane & 3;
    const int wmt = (w / WARPS_N) * MT, wnt = (w % WARPS_N) * NT;

    float acc[MT][NT][4];
    #pragma unroll
    for (int i = 0; i < MT; i++)
        #pragma unroll
        for (int j = 0; j < NT; j++)
            #pragma unroll
            for (int r = 0; r < 4; r++) acc[i][j][r] = 0.f;

    float4 ra[A4];
    float4 rb[B4];

    auto loadA = [&](int k0){
        #pragma unroll
        for (int i = 0; i < A4; i++) {
            int f = i * THREADS + tid;
            int m = f / SL, kq = f % SL;
            int gm = m0 + m;
            if (gm < M) ra[i] = *(const float4*)&A[(long long)gm * lda + k0 + kq * 4];
            else        ra[i] = make_float4(0.f, 0.f, 0.f, 0.f);
        }
    };
    auto loadB = [&](int k0){
        #pragma unroll
        for (int i = 0; i < B4; i++) {
            int f = i * THREADS + tid;
            int n = f / SL, kq = f % SL;
            int gn = n0 + n;
            rb[i] = (gn < N) ? *(const float4*)&B[(long long)gn * ldb + k0 + kq * 4]
                             : make_float4(0.f, 0.f, 0.f, 0.f);
        }
    };
    auto storeA = [&](int s){
        #pragma unroll
        for (int i = 0; i < A4; i++) {
            int f = i * THREADS + tid;
            int m = f / SL, kq = f % SL;
            int mt = m >> 4, rr = m & 15;
            int pk0 = kq * 2, pk1 = pk0 + 1;
            int kc = pk0 >> 3;
            uint32_t h0, l0, h1, l1;
            split_pair(ra[i].x, ra[i].y, h0, l0);
            split_pair(ra[i].z, ra[i].w, h1, l1);
            int ln0 = ((rr & 7) << 2) | (pk0 & 3);
            int ln1 = ((rr & 7) << 2) | (pk1 & 3);
            int fr  = (rr >> 3) | (((pk0 >> 2) & 1) << 1);
            int a0 = ((kc * MTILES + mt) * 32 + ln0) * 4 + fr;
            int a1 = ((kc * MTILES + mt) * 32 + ln1) * 4 + fr;
            sAh[s][a0] = h0; sAl[s][a0] = l0;
            sAh[s][a1] = h1; sAl[s][a1] = l1;
        }
    };
    auto storeB = [&](int s){
        #pragma unroll
        for (int i = 0; i < B4; i++) {
            int f = i * THREADS + tid;
            int n = f / SL, kq = f % SL;
            int nt = n >> 3;
            int pk0 = kq * 2, pk1 = pk0 + 1;
            int kc = pk0 >> 3;
            uint32_t h0, l0, h1, l1;
            split_pair(rb[i].x, rb[i].y, h0, l0);
            split_pair(rb[i].z, rb[i].w, h1, l1);
            int ln0 = ((n & 7) << 2) | (pk0 & 3);
            int ln1 = ((n & 7) << 2) | (pk1 & 3);
            int fr  = (pk0 >> 2) & 1;
            int a0 = ((kc * NTILES + nt) * 32 + ln0) * 2 + fr;
            int a1 = ((kc * NTILES + nt) * 32 + ln1) * 2 + fr;
            sBh[s][a0] = h0; sBl[s][a0] = l0;
            sBh[s][a1] = h1; sBl[s][a1] = l1;
        }
    };
    auto compute = [&](int s){
        #pragma unroll
        for (int kc = 0; kc < KC; kc++) {
            uint32_t ah[MT][4], al[MT][4];
            #pragma unroll
            for (int i = 0; i < MT; i++) {
                int base = ((kc * MTILES + wmt + i) * 32 + lane) * 4;
                *(uint4*)ah[i] = *(const uint4*)&sAh[s][base];
                *(uint4*)al[i] = *(const uint4*)&sAl[s][base];
            }
            #pragma unroll
            for (int jh = 0; jh < 2; jh++) {
                uint32_t bh[NH][2], bl[NH][2];
                #pragma unroll
                for (int j2 = 0; j2 < NH; j2++) {
                    int base = ((kc * NTILES + wnt + jh * NH + j2) * 32 + lane) * 2;
                    *(uint2*)bh[j2] = *(const uint2*)&sBh[s][base];
                    *(uint2*)bl[j2] = *(const uint2*)&sBl[s][base];
                }
                #pragma unroll
                for (int i = 0; i < MT; i++)
                    #pragma unroll
                    for (int j2 = 0; j2 < NH; j2++) {
                        float* a = acc[i][jh * NH + j2];
                        mma_bf16_k16(a, ah[i], bh[j2]);
                        mma_bf16_k16(a, ah[i], bl[j2]);
                        mma_bf16_k16(a, al[i], bh[j2]);
                    }
            }
        }
    };

    loadA(0); loadB(0);
    storeA(0); storeB(0);
    __syncthreads();
    const int nk = K / BK;
    for (int t = 0; t < nk; t++) {
        int s = t & 1;
        if (t + 1 < nk) { loadA((t + 1) * BK); loadB((t + 1) * BK); }
        compute(s);
        if (t + 1 < nk) {
            storeA(s ^ 1); storeB(s ^ 1);
            __syncthreads();
        }
    }

    #pragma unroll
    for (int i = 0; i < MT; i++) {
        #pragma unroll
        for (int j = 0; j < NT; j++) {
            #pragma unroll
            for (int r = 0; r < 4; r++) {
                int gm = m0 + (wmt + i) * 16 + g + (r >= 2 ? 8 : 0);
                int gn = n0 + (wnt + j) * 8 + 2 * t4 + (r & 1);
                if (gm >= M || gn >= N) continue;
                float v = acc[i][j][r];
                if (epi >= 1) v += bias[gn];
                if (epi == 2)      v = 0.5f * v * (1.0f + erff(v * 0.70710678118654752f));
                else if (epi == 3) v += res[(long long)gm * ldc + gn];
                C[(long long)gm * ldc + gn] = v;
                if (epi == 4 && gn >= 2*DD)
                    res[(long long)(gn - 2*DD) * PP + gm] = v;   // res = vt
            }
        }
    }
}

// ---------------- split-K plain reduce: out = sum_z part[z] ----------------
__global__ void reduce4_kernel(const float* __restrict__ part, float* __restrict__ out){
    int idx = blockIdx.x * blockDim.x + threadIdx.x;   // over PP*DD
    out[idx] = part[idx] + part[idx + PP*DD] + part[idx + 2*PP*DD] + part[idx + 3*PP*DD];
}

// ---------------- split-K reduce + bias (+elementwise res) ----------------
__global__ void reduce4_br_kernel(const float* __restrict__ part, const float* __restrict__ bias,
                                  const float* __restrict__ res, float* __restrict__ out,
                                  int N, int total){
    int idx = blockIdx.x * blockDim.x + threadIdx.x;
    if (idx >= total) return;
    float v = part[idx] + part[idx + total] + part[idx + 2*total] + part[idx + 3*total]
            + bias[idx % N];
    if (res) v += res[idx];
    out[idx] = v;
}

// ---------------- split-K reduce + bias + residual + LayerNorm ----------------
__global__ void reduce4_ln_kernel(const float* __restrict__ part, const float* __restrict__ bias,
                                  float* __restrict__ h,
                                  const float* __restrict__ w, const float* __restrict__ b,
                                  float* __restrict__ y){
    int row = blockIdx.x, tid = threadIdx.x;
    float v[3];
    #pragma unroll
    for (int j = 0; j < 3; j++) {
        int n = tid + j * 256;
        long long idx = (long long)row * DD + n;
        float t = part[idx] + part[idx + (long long)PP*DD] + part[idx + 2LL*PP*DD]
                + part[idx + 3LL*PP*DD] + bias[n] + h[idx];
        h[idx] = t;
        v[j] = t;
    }
    float mu = blockSum(v[0] + v[1] + v[2]) * (1.f / (float)DD);
    float d0 = v[0] - mu, d1 = v[1] - mu, d2 = v[2] - mu;
    float var = blockSum(d0*d0 + d1*d1 + d2*d2) * (1.f / (float)DD);
    float rstd = rsqrtf(var + 1e-5f);
    float* yr = y + (long long)row * DD;
    yr[tid]       = d0 * rstd * w[tid]       + b[tid];
    yr[tid + 256] = d1 * rstd * w[tid + 256] + b[tid + 256];
    yr[tid + 512] = d2 * rstd * w[tid + 512] + b[tid + 512];
}

// ---------------- fused per-patch MHA + masked mean ----------------
#define PA_ST 129
__global__ void patch_attn_kernel(const float* __restrict__ qkv, const int* __restrict__ lengths,
                                  float* __restrict__ out){
    __shared__ float buf0[32 * PA_ST];
    __shared__ float buf1[32 * PA_ST];
    __shared__ float a[32 * 33];
    const int p = blockIdx.x, h = blockIdx.y;
    const int tid = threadIdx.x;
    const int len = lengths[p];
    const float scale = 0.0883883476483184406f;
    const float* base = qkv + (long long)p * 32 * 1536 + h * 128;

    #pragma unroll 8
    for (int i = 0; i < 32; i++) {
        int idx = i * 128 + tid; int l = idx >> 7, e = idx & 127;
        buf0[l * PA_ST + e] = base[l * 1536 + e] * scale;
        buf1[l * PA_ST + e] = base[l * 1536 + 512 + e];
    }
    __syncthreads();
    #pragma unroll
    for (int i = 0; i < 8; i++) {
        int idx = i * 128 + tid; int row = idx >> 5, col = idx & 31;
        float d = 0.f;
        #pragma unroll 16
        for (int kk = 0; kk < 128; kk++)
            d += buf0[row * PA_ST + kk] * buf1[col * PA_ST + kk];
        a[row * 33 + col] = (col < len) ? d : -1e9f;
    }
    __syncthreads();
    if (tid < 32) {
        float m = -1e30f;
        #pragma unroll
        for (int c = 0; c < 32; c++) m = fmaxf(m, a[tid * 33 + c]);
        float s = 0.f;
        #pragma unroll
        for (int c = 0; c < 32; c++) { float e = expf(a[tid * 33 + c] - m); a[tid * 33 + c] = e; s += e; }
        float inv = 1.f / s;
        #pragma unroll
        for (int c = 0; c < 32; c++) a[tid * 33 + c] *= inv;
    }
    __syncthreads();
    #pragma unroll 8
    for (int i = 0; i < 32; i++) {
        int idx = i * 128 + tid; int l = idx >> 7, e = idx & 127;
        buf0[l * PA_ST + e] = base[l * 1536 + 1024 + e];
    }
    __syncthreads();
    const int row = tid & 31, eb = (tid >> 5) * 32;
    float acc[32];
    #pragma unroll
    for (int e = 0; e < 32; e++) acc[e] = 0.f;
    for (int j = 0; j < 32; j++) {
        float aj = a[row * 33 + j];
        #pragma unroll
        for (int e = 0; e < 32; e++) acc[e] += aj * buf0[j * PA_ST + eb + e];
    }
    #pragma unroll
    for (int e = 0; e < 32; e++) buf1[row * PA_ST + eb + e] = acc[e];
    __syncthreads();
    {
        float s = 0.f;
        for (int l = 0; l < len; l++) s += buf1[l * PA_ST + tid];
        out[(long long)p * 512 + h * 128 + tid] = s * (1.f / (float)len);
    }
}

// ---------------- layer norm ----------------
__global__ void ln_kernel(const float* __restrict__ x, const float* __restrict__ w,
                          const float* __restrict__ b, float* __restrict__ y){
    int row = blockIdx.x, tid = threadIdx.x;
    const float* xr = x + (long long)row * DD;
    float v0 = xr[tid], v1 = xr[tid + 256], v2 = xr[tid + 512];
    float mu = blockSum(v0 + v1 + v2) * (1.f / (float)DD);
    float d0 = v0 - mu, d1 = v1 - mu, d2 = v2 - mu;
    float var = blockSum(d0 * d0 + d1 * d1 + d2 * d2) * (1.f / (float)DD);
    float rstd = rsqrtf(var + 1e-5f);
    float* yr = y + (long long)row * DD;
    yr[tid]       = d0 * rstd * w[tid]       + b[tid];
    yr[tid + 256] = d1 * rstd * w[tid + 256] + b[tid + 256];
    yr[tid + 512] = d2 * rstd * w[tid + 512] + b[tid + 512];
}

// ---------------- row softmax ----------------
__global__ void softmax_kernel(float* __restrict__ s, float scale){
    float* r = s + (long long)blockIdx.x * 1024;
    int tid = threadIdx.x;
    float v[4];
    float m = -1e30f;
    #pragma unroll
    for (int i = 0; i < 4; i++) { v[i] = r[tid + i * 256]; m = fmaxf(m, v[i]); }
    m = blockMax(m);
    float sum = 0.f;
    #pragma unroll
    for (int i = 0; i < 4; i++) { v[i] = expf((v[i] - m) * scale); sum += v[i]; }
    sum = blockSum(sum);
    float inv = 1.f / sum;
    #pragma unroll
    for (int i = 0; i < 4; i++) r[tid + i * 256] = v[i] * inv;
}

// ---------------- host-side launch helpers ----------------
static void gemm128(const float* A, const float* B, const float* bias, float* res, float* C,
                    int M, int N, int K, int lda, int ldb, int ldc,
                    long long bA, long long bB, long long bC, int batch, int epi){
    dim3 grid((N + 127) / 128, (M + 127) / 128, batch);
    gemmbf_kernel<128,128,16,2,2,2><<<grid, 128>>>(A,B,bias,res,C,M,N,K,lda,ldb,ldc,bA,bB,bC,epi,
        1, 0, 0, 0);
}
static void gemm64(const float* A, const float* B, const float* bias, float* res, float* C,
                   int M, int N, int K, int lda, int ldb, int ldc,
                   long long bA, long long bB, long long bC, int batch, int epi){
    dim3 grid((N + 63) / 64, (M + 63) / 64, batch);
    gemmbf_kernel<64,64,32,2,2,3><<<grid, 128>>>(A,B,bias,res,C,M,N,K,lda,ldb,ldc,bA,bB,bC,epi,
        1, 0, 0, 0);
}
static void gemm64_ks(const float* A, const float* B, float* C,
                      int M, int N, int Ksub, int lda, int ldb, int ldc,
                      long long bA, long long bB, long long bC, int batch, int ksplit,
                      long long aOff, long long bOff, long long cOff){
    dim3 grid((N + 63) / 64, (M + 63) / 64, batch * ksplit);
    gemmbf_kernel<64,64,32,2,2,3><<<grid, 128>>>(A,B,nullptr,nullptr,C,M,N,Ksub,lda,ldb,ldc,bA,bB,bC,0,
        ksplit, aOff, bOff, cOff);
}

extern "C" void kernel_launch(void* const* d_in, const int* in_sizes, int n_in,
                              void* d_out, int out_size){
    const int*   tokens   = (const int*)  d_in[0];
    const int*   lengths  = (const int*)  d_in[1];
    const float* byte_emb = (const float*)d_in[2];
    const float* lpos     = (const float*)d_in[3];
    const float* ppos     = (const float*)d_in[4];
    const float* pa_qkv_w = (const float*)d_in[5];
    const float* pa_qkv_b = (const float*)d_in[6];
    const float* pa_out_w = (const float*)d_in[7];
    const float* pa_out_b = (const float*)d_in[8];
    const float* proj_w   = (const float*)d_in[9];
    const float* proj_b   = (const float*)d_in[10];
    const float* lw_qkv   = (const float*)d_in[11];
    const float* lb_qkv   = (const float*)d_in[12];
    const float* lw_out   = (const float*)d_in[13];
    const float* lb_out   = (const float*)d_in[14];
    const float* ln1w     = (const float*)d_in[15];
    const float* ln1b     = (const float*)d_in[16];
    const float* ln2w     = (const float*)d_in[17];
    const float* ln2b     = (const float*)d_in[18];
    const float* ffw1     = (const float*)d_in[19];
    const float* ffb1     = (const float*)d_in[20];
    const float* ffw2     = (const float*)d_in[21];
    const float* ffb2     = (const float*)d_in[22];
    const float* lnfw     = (const float*)d_in[23];
    const float* lnfb     = (const float*)d_in[24];
    float* out = (float*)d_out;

    float *emb, *qkv, *patch, *patcho, *h, *hn, *qkvt, *scores, *attnt, *ff, *vt, *split;
    cudaGetSymbolAddress((void**)&emb,     g_emb);
    cudaGetSymbolAddress((void**)&qkv,     g_qkv);
    cudaGetSymbolAddress((void**)&patch,   g_patch);
    cudaGetSymbolAddress((void**)&patcho,  g_patcho);
    cudaGetSymbolAddress((void**)&h,       g_h);
    cudaGetSymbolAddress((void**)&hn,      g_hn);
    cudaGetSymbolAddress((void**)&qkvt,    g_qkvt);
    cudaGetSymbolAddress((void**)&scores,  g_scores);
    cudaGetSymbolAddress((void**)&attnt,   g_attnt);
    cudaGetSymbolAddress((void**)&ff,      g_ff);
    cudaGetSymbolAddress((void**)&vt,      g_vt);
    cudaGetSymbolAddress((void**)&split,   g_split);

    // 1) byte embedding + mask
    embed_kernel<<<(TT * EE) / 256, 256>>>(tokens, lengths, byte_emb, lpos, emb);

    // 2) patch-attention QKV
    gemm128(emb, pa_qkv_w, pa_qkv_b, nullptr, qkv,
            TT, 3*EE, EE, EE, EE, 3*EE, 0, 0, 0, 1, 1);

    // 3) fused per-patch attention + masked mean
    patch_attn_kernel<<<dim3(PP, 4), 128>>>(qkv, lengths, patch);

    // 4) patch out-proj: split-K x4 (K=512 -> 128/chunk, 512 CTAs)
    gemm64_ks(patch, pa_out_w, split,
              PP, EE, EE/4, EE, EE, EE,
              0, 0, 0, 1, 4, EE/4, EE/4, (long long)PP * EE);
    reduce4_br_kernel<<<(PP * EE) / 256, 256>>>(split, pa_out_b, nullptr, patcho, EE, PP * EE);

    // 5) project to D + ppos: split-K x4 (K=512, 768 CTAs)
    gemm64_ks(patcho, proj_w, split,
              PP, DD, EE/4, EE, EE, DD,
              0, 0, 0, 1, 4, EE/4, EE/4, (long long)PP * DD);
    reduce4_br_kernel<<<(PP * DD) / 256, 256>>>(split, proj_b, ppos, h, DD, PP * DD);

    const float tr_scale = 0.1020620726159657588f;   // 1/sqrt(96)

    // LN1 of layer 0
    ln_kernel<<<PP, 256>>>(h, ln1w, ln1b, hn);

    for (int i = 0; i < NLAY; i++) {
        const float* qkv_w = lw_qkv + (size_t)i * 3 * DD * DD;
        const float* qkv_b = lb_qkv + (size_t)i * 3 * DD;
        const float* out_w = lw_out + (size_t)i * DD * DD;
        const float* out_b = lb_out + (size_t)i * DD;
        const float* f1w   = ffw1  + (size_t)i * FFD * DD;
        const float* f1b   = ffb1  + (size_t)i * FFD;
        const float* f2w   = ffw2  + (size_t)i * DD * FFD;
        const float* f2b   = ffb2  + (size_t)i * DD;

        // QKV with fused V-transpose into vt (epi=4, res=vt)
        gemm64(hn, qkv_w, qkv_b, vt, qkvt,
               PP, 3*DD, DD, DD, DD, 3*DD, 0, 0, 0, 1, 4);
        // scores per head (batched over 8 heads)
        gemm128(qkvt, qkvt + DD, nullptr, nullptr, scores,
                PP, PP, 96, 3*DD, 3*DD, PP,
                96, 96, (long long)PP * PP, 8, 0);
        softmax_kernel<<<8 * PP, 256>>>(scores, tr_scale);
        // AV split-K x4: 8 heads x 4 k-chunks of 256 -> 1024 CTAs
        gemm64_ks(scores, vt, split,
                  PP, 96, PP/4, PP, PP, DD,
                  (long long)PP * PP, (long long)96 * PP, 96, 8, 4,
                  PP/4, PP/4, (long long)PP * DD);
        reduce4_kernel<<<(PP * DD) / 256, 256>>>(split, attnt);
        // out-proj split-K x4 (bias+residual+LN2 in reduce)
        gemm64_ks(attnt, out_w, split,
                  PP, DD, DD/4, DD, DD, DD,
                  0, 0, 0, 1, 4,
                  DD/4, DD/4, (long long)PP * DD);
        reduce4_ln_kernel<<<PP, 256>>>(split, out_b, h,
                                       ln2w + (size_t)i * DD, ln2b + (size_t)i * DD, hn);
        // FF1 + gelu
        gemm64(hn, f1w, f1b, nullptr, ff,
               PP, FFD, DD, DD, DD, FFD, 0, 0, 0, 1, 2);
        // FF2 split-K x4
        gemm64_ks(ff, f2w, split,
                  PP, DD, FFD/4, FFD, FFD, DD,
                  0, 0, 0, 1, 4,
                  FFD/4, FFD/4, (long long)PP * DD);
        // fused reduce + residual + next LN
        if (i + 1 < NLAY) {
            reduce4_ln_kernel<<<PP, 256>>>(split, f2b, h,
                                           ln1w + (size_t)(i+1) * DD, ln1b + (size_t)(i+1) * DD, hn);
        } else {
            reduce4_ln_kernel<<<PP, 256>>>(split, f2b, h, lnfw, lnfb, out);
        }
    }
}

// round 16
// speedup vs baseline: 1.0587x; 1.0587x over previous
#include <cuda_runtime.h>
#include <math.h>
#include <stdint.h>

#define PP 1024
#define LL 32
#define EE 512
#define DD 768
#define NLAY 6
#define FFD 3072
#define TT (PP*LL)

// ---------------- scratch ----------------
__device__ float g_emb[TT*EE];
__device__ float g_qkv[TT*3*EE];
__device__ float g_patch[PP*EE];
__device__ float g_patcho[PP*EE];
__device__ float g_h[PP*DD];
__device__ float g_hn[PP*DD];
__device__ float g_qkvt[PP*3*DD];
__device__ float g_scores[8*PP*PP];
__device__ float g_attnt[PP*DD];
__device__ float g_ff[PP*FFD];
__device__ float g_vt[DD*PP];
__device__ float g_split[4*PP*DD];

// ---------------- block reductions ----------------
__device__ __forceinline__ float blockSum(float v){
    __shared__ float sh[32];
    int lane = threadIdx.x & 31, wid = threadIdx.x >> 5, nw = blockDim.x >> 5;
    #pragma unroll
    for (int o = 16; o; o >>= 1) v += __shfl_xor_sync(0xffffffffu, v, o);
    if (lane == 0) sh[wid] = v;
    __syncthreads();
    float t = (lane < nw) ? sh[lane] : 0.f;
    #pragma unroll
    for (int o = 16; o; o >>= 1) t += __shfl_xor_sync(0xffffffffu, t, o);
    __syncthreads();
    return t;
}
__device__ __forceinline__ float blockMax(float v){
    __shared__ float sh[32];
    int lane = threadIdx.x & 31, wid = threadIdx.x >> 5, nw = blockDim.x >> 5;
    #pragma unroll
    for (int o = 16; o; o >>= 1) v = fmaxf(v, __shfl_xor_sync(0xffffffffu, v, o));
    if (lane == 0) sh[wid] = v;
    __syncthreads();
    float t = (lane < nw) ? sh[lane] : -1e30f;
    #pragma unroll
    for (int o = 16; o; o >>= 1) t = fmaxf(t, __shfl_xor_sync(0xffffffffu, t, o));
    __syncthreads();
    return t;
}

// ---------------- embedding + mask ----------------
__global__ void embed_kernel(const int* __restrict__ tokens, const int* __restrict__ lengths,
                             const float* __restrict__ bemb, const float* __restrict__ lpos,
                             float* __restrict__ out){
    int idx = blockIdx.x * blockDim.x + threadIdx.x;
    if (idx >= TT * EE) return;
    int e = idx & (EE - 1);
    int t = idx >> 9;
    int l = t & (LL - 1);
    int p = t >> 5;
    float v = 0.f;
    if (l < lengths[p]) {
        int tok = tokens[t];
        v = bemb[tok * EE + e] + lpos[l * EE + e];
    }
    out[idx] = v;
}

// ---------------- bf16 helpers ----------------
__device__ __forceinline__ uint32_t pack_bf16(float v0, float v1){
    uint32_t r; asm("cvt.rn.bf16x2.f32 %0, %1, %2;" : "=r"(r) : "f"(v1), "f"(v0)); return r;
}
__device__ __forceinline__ void split_pair(float v0, float v1, uint32_t &hi, uint32_t &lo){
    hi = pack_bf16(v0, v1);
    float h0 = __uint_as_float(hi << 16);
    float h1 = __uint_as_float(hi & 0xffff0000u);
    lo = pack_bf16(v0 - h0, v1 - h1);
}
__device__ __forceinline__ void mma_bf16_k16(float* c, const uint32_t* a, const uint32_t* b){
    asm("mma.sync.aligned.m16n8k16.row.col.f32.bf16.bf16.f32 "
        "{%0,%1,%2,%3}, {%4,%5,%6,%7}, {%8,%9}, {%0,%1,%2,%3};"
        : "+f"(c[0]), "+f"(c[1]), "+f"(c[2]), "+f"(c[3])
        : "r"(a[0]), "r"(a[1]), "r"(a[2]), "r"(a[3]), "r"(b[0]), "r"(b[1]));
}

// ---------------- split-bf16 GEMM (3 MMAs per k16), fragment-order smem ----------------
// C[M,N] = A[M,K] * B[N,K]^T (+epi). K % BK == 0.
// batch via blockIdx.z = zh*ksplit + zk.
// epi: 0 none, 1 bias, 2 bias+gelu(exact), 3 bias+residual
template<int BM, int BN, int BK, int WARPS_M, int WARPS_N, int MINB>
__global__ void __launch_bounds__(WARPS_M*WARPS_N*32, MINB)
gemmbf_kernel(const float* __restrict__ A, const float* __restrict__ B,
              const float* __restrict__ bias, const float* __restrict__ res,
              float* __restrict__ C,
              int M, int N, int K,
              int lda, int ldb, int ldc,
              long long bA, long long bB, long long bC, int epi,
              int ksplit, long long aOff, long long bOff, long long cOff){
    constexpr int THREADS = WARPS_M * WARPS_N * 32;
    constexpr int KC = BK / 16;
    constexpr int SL = BK / 4;
    constexpr int WM = BM / WARPS_M, WN = BN / WARPS_N;
    constexpr int MT = WM / 16, NT = WN / 8;
    constexpr int NH = NT / 2;
    constexpr int MTILES = BM / 16, NTILES = BN / 8;
    constexpr int ASZ = KC * MTILES * 32 * 4;
    constexpr int BSZ = KC * NTILES * 32 * 2;
    constexpr int A4 = BM * SL / THREADS;
    constexpr int B4 = BN * SL / THREADS;

    __shared__ alignas(16) uint32_t sAh[2][ASZ];
    __shared__ alignas(16) uint32_t sAl[2][ASZ];
    __shared__ alignas(16) uint32_t sBh[2][BSZ];
    __shared__ alignas(16) uint32_t sBl[2][BSZ];

    const int tid = threadIdx.x;
    const int zh = blockIdx.z / ksplit, zk = blockIdx.z % ksplit;
    A += (long long)zh * bA + (long long)zk * aOff;
    B += (long long)zh * bB + (long long)zk * bOff;
    C += (long long)zh * bC + (long long)zk * cOff;
    const int m0 = blockIdx.y * BM, n0 = blockIdx.x * BN;
    const int w = tid >> 5, lane = tid & 31;
    const int g = lane >> 2, t4 = lane & 3;
    const int wmt = (w / WARPS_N) * MT, wnt = (w % WARPS_N) * NT;

    float acc[MT][NT][4];
    #pragma unroll
    for (int i = 0; i < MT; i++)
        #pragma unroll
        for (int j = 0; j < NT; j++)
            #pragma unroll
            for (int r = 0; r < 4; r++) acc[i][j][r] = 0.f;

    float4 ra[A4];
    float4 rb[B4];

    auto loadA = [&](int k0){
        #pragma unroll
        for (int i = 0; i < A4; i++) {
            int f = i * THREADS + tid;
            int m = f / SL, kq = f % SL;
            int gm = m0 + m;
            if (gm < M) ra[i] = *(const float4*)&A[(long long)gm * lda + k0 + kq * 4];
            else        ra[i] = make_float4(0.f, 0.f, 0.f, 0.f);
        }
    };
    auto loadB = [&](int k0){
        #pragma unroll
        for (int i = 0; i < B4; i++) {
            int f = i * THREADS + tid;
            int n = f / SL, kq = f % SL;
            int gn = n0 + n;
            rb[i] = (gn < N) ? *(const float4*)&B[(long long)gn * ldb + k0 + kq * 4]
                             : make_float4(0.f, 0.f, 0.f, 0.f);
        }
    };
    auto storeA = [&](int s){
        #pragma unroll
        for (int i = 0; i < A4; i++) {
            int f = i * THREADS + tid;
            int m = f / SL, kq = f % SL;
            int mt = m >> 4, rr = m & 15;
            int pk0 = kq * 2, pk1 = pk0 + 1;
            int kc = pk0 >> 3;
            uint32_t h0, l0, h1, l1;
            split_pair(ra[i].x, ra[i].y, h0, l0);
            split_pair(ra[i].z, ra[i].w, h1, l1);
            int ln0 = ((rr & 7) << 2) | (pk0 & 3);
            int ln1 = ((rr & 7) << 2) | (pk1 & 3);
            int fr  = (rr >> 3) | (((pk0 >> 2) & 1) << 1);
            int a0 = ((kc * MTILES + mt) * 32 + ln0) * 4 + fr;
            int a1 = ((kc * MTILES + mt) * 32 + ln1) * 4 + fr;
            sAh[s][a0] = h0; sAl[s][a0] = l0;
            sAh[s][a1] = h1; sAl[s][a1] = l1;
        }
    };
    auto storeB = [&](int s){
        #pragma unroll
        for (int i = 0; i < B4; i++) {
            int f = i * THREADS + tid;
            int n = f / SL, kq = f % SL;
            int nt = n >> 3;
            int pk0 = kq * 2, pk1 = pk0 + 1;
            int kc = pk0 >> 3;
            uint32_t h0, l0, h1, l1;
            split_pair(rb[i].x, rb[i].y, h0, l0);
            split_pair(rb[i].z, rb[i].w, h1, l1);
            int ln0 = ((n & 7) << 2) | (pk0 & 3);
            int ln1 = ((n & 7) << 2) | (pk1 & 3);
            int fr  = (pk0 >> 2) & 1;
            int a0 = ((kc * NTILES + nt) * 32 + ln0) * 2 + fr;
            int a1 = ((kc * NTILES + nt) * 32 + ln1) * 2 + fr;
            sBh[s][a0] = h0; sBl[s][a0] = l0;
            sBh[s][a1] = h1; sBl[s][a1] = l1;
        }
    };
    auto compute = [&](int s){
        #pragma unroll
        for (int kc = 0; kc < KC; kc++) {
            uint32_t ah[MT][4], al[MT][4];
            #pragma unroll
            for (int i = 0; i < MT; i++) {
                int base = ((kc * MTILES + wmt + i) * 32 + lane) * 4;
                *(uint4*)ah[i] = *(const uint4*)&sAh[s][base];
                *(uint4*)al[i] = *(const uint4*)&sAl[s][base];
            }
            #pragma unroll
            for (int jh = 0; jh < 2; jh++) {
                uint32_t bh[NH][2], bl[NH][2];
                #pragma unroll
                for (int j2 = 0; j2 < NH; j2++) {
                    int base = ((kc * NTILES + wnt + jh * NH + j2) * 32 + lane) * 2;
                    *(uint2*)bh[j2] = *(const uint2*)&sBh[s][base];
                    *(uint2*)bl[j2] = *(const uint2*)&sBl[s][base];
                }
                #pragma unroll
                for (int i = 0; i < MT; i++)
                    #pragma unroll
                    for (int j2 = 0; j2 < NH; j2++) {
                        float* a = acc[i][jh * NH + j2];
                        mma_bf16_k16(a, ah[i], bh[j2]);
                        mma_bf16_k16(a, ah[i], bl[j2]);
                        mma_bf16_k16(a, al[i], bh[j2]);
                    }
            }
        }
    };

    loadA(0); loadB(0);
    storeA(0); storeB(0);
    __syncthreads();
    const int nk = K / BK;
    for (int t = 0; t < nk; t++) {
        int s = t & 1;
        if (t + 1 < nk) { loadA((t + 1) * BK); loadB((t + 1) * BK); }
        compute(s);
        if (t + 1 < nk) {
            storeA(s ^ 1); storeB(s ^ 1);
            __syncthreads();
        }
    }

    #pragma unroll
    for (int i = 0; i < MT; i++) {
        #pragma unroll
        for (int j = 0; j < NT; j++) {
            #pragma unroll
            for (int r = 0; r < 4; r++) {
                int gm = m0 + (wmt + i) * 16 + g + (r >= 2 ? 8 : 0);
                int gn = n0 + (wnt + j) * 8 + 2 * t4 + (r & 1);
                if (gm >= M || gn >= N) continue;
                float v = acc[i][j][r];
                if (epi >= 1) v += bias[gn];
                if (epi == 2)      v = 0.5f * v * (1.0f + erff(v * 0.70710678118654752f));
                else if (epi == 3) v += res[(long long)gm * ldc + gn];
                C[(long long)gm * ldc + gn] = v;
            }
        }
    }
}

// ---------------- split-K plain reduce: out = sum_z part[z] ----------------
__global__ void reduce4_kernel(const float* __restrict__ part, float* __restrict__ out){
    int idx = blockIdx.x * blockDim.x + threadIdx.x;   // over PP*DD
    out[idx] = part[idx] + part[idx + PP*DD] + part[idx + 2*PP*DD] + part[idx + 3*PP*DD];
}

// ---------------- split-K reduce + bias (+elementwise res) ----------------
__global__ void reduce4_br_kernel(const float* __restrict__ part, const float* __restrict__ bias,
                                  const float* __restrict__ res, float* __restrict__ out,
                                  int N, int total){
    int idx = blockIdx.x * blockDim.x + threadIdx.x;
    if (idx >= total) return;
    float v = part[idx] + part[idx + total] + part[idx + 2*total] + part[idx + 3*total]
            + bias[idx % N];
    if (res) v += res[idx];
    out[idx] = v;
}

// ---------------- split-K reduce + bias + residual + LayerNorm ----------------
__global__ void reduce4_ln_kernel(const float* __restrict__ part, const float* __restrict__ bias,
                                  float* __restrict__ h,
                                  const float* __restrict__ w, const float* __restrict__ b,
                                  float* __restrict__ y){
    int row = blockIdx.x, tid = threadIdx.x;
    float v[3];
    #pragma unroll
    for (int j = 0; j < 3; j++) {
        int n = tid + j * 256;
        long long idx = (long long)row * DD + n;
        float t = part[idx] + part[idx + (long long)PP*DD] + part[idx + 2LL*PP*DD]
                + part[idx + 3LL*PP*DD] + bias[n] + h[idx];
        h[idx] = t;
        v[j] = t;
    }
    float mu = blockSum(v[0] + v[1] + v[2]) * (1.f / (float)DD);
    float d0 = v[0] - mu, d1 = v[1] - mu, d2 = v[2] - mu;
    float var = blockSum(d0*d0 + d1*d1 + d2*d2) * (1.f / (float)DD);
    float rstd = rsqrtf(var + 1e-5f);
    float* yr = y + (long long)row * DD;
    yr[tid]       = d0 * rstd * w[tid]       + b[tid];
    yr[tid + 256] = d1 * rstd * w[tid + 256] + b[tid + 256];
    yr[tid + 512] = d2 * rstd * w[tid + 512] + b[tid + 512];
}

// ---------------- fused per-patch MHA + masked mean ----------------
#define PA_ST 129
__global__ void patch_attn_kernel(const float* __restrict__ qkv, const int* __restrict__ lengths,
                                  float* __restrict__ out){
    __shared__ float buf0[32 * PA_ST];
    __shared__ float buf1[32 * PA_ST];
    __shared__ float a[32 * 33];
    const int p = blockIdx.x, h = blockIdx.y;
    const int tid = threadIdx.x;
    const int len = lengths[p];
    const float scale = 0.0883883476483184406f;
    const float* base = qkv + (long long)p * 32 * 1536 + h * 128;

    #pragma unroll 8
    for (int i = 0; i < 32; i++) {
        int idx = i * 128 + tid; int l = idx >> 7, e = idx & 127;
        buf0[l * PA_ST + e] = base[l * 1536 + e] * scale;
        buf1[l * PA_ST + e] = base[l * 1536 + 512 + e];
    }
    __syncthreads();
    #pragma unroll
    for (int i = 0; i < 8; i++) {
        int idx = i * 128 + tid; int row = idx >> 5, col = idx & 31;
        float d = 0.f;
        #pragma unroll 16
        for (int kk = 0; kk < 128; kk++)
            d += buf0[row * PA_ST + kk] * buf1[col * PA_ST + kk];
        a[row * 33 + col] = (col < len) ? d : -1e9f;
    }
    __syncthreads();
    if (tid < 32) {
        float m = -1e30f;
        #pragma unroll
        for (int c = 0; c < 32; c++) m = fmaxf(m, a[tid * 33 + c]);
        float s = 0.f;
        #pragma unroll
        for (int c = 0; c < 32; c++) { float e = expf(a[tid * 33 + c] - m); a[tid * 33 + c] = e; s += e; }
        float inv = 1.f / s;
        #pragma unroll
        for (int c = 0; c < 32; c++) a[tid * 33 + c] *= inv;
    }
    __syncthreads();
    #pragma unroll 8
    for (int i = 0; i < 32; i++) {
        int idx = i * 128 + tid; int l = idx >> 7, e = idx & 127;
        buf0[l * PA_ST + e] = base[l * 1536 + 1024 + e];
    }
    __syncthreads();
    const int row = tid & 31, eb = (tid >> 5) * 32;
    float acc[32];
    #pragma unroll
    for (int e = 0; e < 32; e++) acc[e] = 0.f;
    for (int j = 0; j < 32; j++) {
        float aj = a[row * 33 + j];
        #pragma unroll
        for (int e = 0; e < 32; e++) acc[e] += aj * buf0[j * PA_ST + eb + e];
    }
    #pragma unroll
    for (int e = 0; e < 32; e++) buf1[row * PA_ST + eb + e] = acc[e];
    __syncthreads();
    {
        float s = 0.f;
        for (int l = 0; l < len; l++) s += buf1[l * PA_ST + tid];
        out[(long long)p * 512 + h * 128 + tid] = s * (1.f / (float)len);
    }
}

// ---------------- layer norm ----------------
__global__ void ln_kernel(const float* __restrict__ x, const float* __restrict__ w,
                          const float* __restrict__ b, float* __restrict__ y){
    int row = blockIdx.x, tid = threadIdx.x;
    const float* xr = x + (long long)row * DD;
    float v0 = xr[tid], v1 = xr[tid + 256], v2 = xr[tid + 512];
    float mu = blockSum(v0 + v1 + v2) * (1.f / (float)DD);
    float d0 = v0 - mu, d1 = v1 - mu, d2 = v2 - mu;
    float var = blockSum(d0 * d0 + d1 * d1 + d2 * d2) * (1.f / (float)DD);
    float rstd = rsqrtf(var + 1e-5f);
    float* yr = y + (long long)row * DD;
    yr[tid]       = d0 * rstd * w[tid]       + b[tid];
    yr[tid + 256] = d1 * rstd * w[tid + 256] + b[tid + 256];
    yr[tid + 512] = d2 * rstd * w[tid + 512] + b[tid + 512];
}

// ---------------- row softmax ----------------
__global__ void softmax_kernel(float* __restrict__ s, float scale){
    float* r = s + (long long)blockIdx.x * 1024;
    int tid = threadIdx.x;
    float v[4];
    float m = -1e30f;
    #pragma unroll
    for (int i = 0; i < 4; i++) { v[i] = r[tid + i * 256]; m = fmaxf(m, v[i]); }
    m = blockMax(m);
    float sum = 0.f;
    #pragma unroll
    for (int i = 0; i < 4; i++) { v[i] = expf((v[i] - m) * scale); sum += v[i]; }
    sum = blockSum(sum);
    float inv = 1.f / sum;
    #pragma unroll
    for (int i = 0; i < 4; i++) r[tid + i * 256] = v[i] * inv;
}

// ---------------- V transpose ----------------
__global__ void transpose_v_kernel(const float* __restrict__ qkvt, float* __restrict__ vt){
    __shared__ float t[32][33];
    int token0 = blockIdx.x * 32, v0 = blockIdx.y * 32;
    int tx = threadIdx.x & 31, ty = threadIdx.x >> 5;
    #pragma unroll
    for (int r = ty; r < 32; r += 8)
        t[r][tx] = qkvt[(long long)(token0 + r) * (3*DD) + 2*DD + v0 + tx];
    __syncthreads();
    #pragma unroll
    for (int r = ty; r < 32; r += 8)
        vt[(long long)(v0 + r) * PP + token0 + tx] = t[tx][r];
}

// ---------------- host-side launch helpers ----------------
static void gemm128(const float* A, const float* B, const float* bias, const float* res, float* C,
                    int M, int N, int K, int lda, int ldb, int ldc,
                    long long bA, long long bB, long long bC, int batch, int epi){
    dim3 grid((N + 127) / 128, (M + 127) / 128, batch);
    gemmbf_kernel<128,128,16,2,2,2><<<grid, 128>>>(A,B,bias,res,C,M,N,K,lda,ldb,ldc,bA,bB,bC,epi,
        1, 0, 0, 0);
}
static void gemm64(const float* A, const float* B, const float* bias, const float* res, float* C,
                   int M, int N, int K, int lda, int ldb, int ldc,
                   long long bA, long long bB, long long bC, int batch, int epi){
    dim3 grid((N + 63) / 64, (M + 63) / 64, batch);
    gemmbf_kernel<64,64,32,2,2,3><<<grid, 128>>>(A,B,bias,res,C,M,N,K,lda,ldb,ldc,bA,bB,bC,epi,
        1, 0, 0, 0);
}
static void gemm64_ks(const float* A, const float* B, float* C,
                      int M, int N, int Ksub, int lda, int ldb, int ldc,
                      long long bA, long long bB, long long bC, int batch, int ksplit,
                      long long aOff, long long bOff, long long cOff){
    dim3 grid((N + 63) / 64, (M + 63) / 64, batch * ksplit);
    gemmbf_kernel<64,64,32,2,2,3><<<grid, 128>>>(A,B,nullptr,nullptr,C,M,N,Ksub,lda,ldb,ldc,bA,bB,bC,0,
        ksplit, aOff, bOff, cOff);
}

extern "C" void kernel_launch(void* const* d_in, const int* in_sizes, int n_in,
                              void* d_out, int out_size){
    const int*   tokens   = (const int*)  d_in[0];
    const int*   lengths  = (const int*)  d_in[1];
    const float* byte_emb = (const float*)d_in[2];
    const float* lpos     = (const float*)d_in[3];
    const float* ppos     = (const float*)d_in[4];
    const float* pa_qkv_w = (const float*)d_in[5];
    const float* pa_qkv_b = (const float*)d_in[6];
    const float* pa_out_w = (const float*)d_in[7];
    const float* pa_out_b = (const float*)d_in[8];
    const float* proj_w   = (const float*)d_in[9];
    const float* proj_b   = (const float*)d_in[10];
    const float* lw_qkv   = (const float*)d_in[11];
    const float* lb_qkv   = (const float*)d_in[12];
    const float* lw_out   = (const float*)d_in[13];
    const float* lb_out   = (const float*)d_in[14];
    const float* ln1w     = (const float*)d_in[15];
    const float* ln1b     = (const float*)d_in[16];
    const float* ln2w     = (const float*)d_in[17];
    const float* ln2b     = (const float*)d_in[18];
    const float* ffw1     = (const float*)d_in[19];
    const float* ffb1     = (const float*)d_in[20];
    const float* ffw2     = (const float*)d_in[21];
    const float* ffb2     = (const float*)d_in[22];
    const float* lnfw     = (const float*)d_in[23];
    const float* lnfb     = (const float*)d_in[24];
    float* out = (float*)d_out;

    float *emb, *qkv, *patch, *patcho, *h, *hn, *qkvt, *scores, *attnt, *ff, *vt, *split;
    cudaGetSymbolAddress((void**)&emb,     g_emb);
    cudaGetSymbolAddress((void**)&qkv,     g_qkv);
    cudaGetSymbolAddress((void**)&patch,   g_patch);
    cudaGetSymbolAddress((void**)&patcho,  g_patcho);
    cudaGetSymbolAddress((void**)&h,       g_h);
    cudaGetSymbolAddress((void**)&hn,      g_hn);
    cudaGetSymbolAddress((void**)&qkvt,    g_qkvt);
    cudaGetSymbolAddress((void**)&scores,  g_scores);
    cudaGetSymbolAddress((void**)&attnt,   g_attnt);
    cudaGetSymbolAddress((void**)&ff,      g_ff);
    cudaGetSymbolAddress((void**)&vt,      g_vt);
    cudaGetSymbolAddress((void**)&split,   g_split);

    // 1) byte embedding + mask
    embed_kernel<<<(TT * EE) / 256, 256>>>(tokens, lengths, byte_emb, lpos, emb);

    // 2) patch-attention QKV
    gemm128(emb, pa_qkv_w, pa_qkv_b, nullptr, qkv,
            TT, 3*EE, EE, EE, EE, 3*EE, 0, 0, 0, 1, 1);

    // 3) fused per-patch attention + masked mean
    patch_attn_kernel<<<dim3(PP, 4), 128>>>(qkv, lengths, patch);

    // 4) patch out-proj: split-K x4 (K=512 -> 128/chunk, 512 CTAs)
    gemm64_ks(patch, pa_out_w, split,
              PP, EE, EE/4, EE, EE, EE,
              0, 0, 0, 1, 4, EE/4, EE/4, (long long)PP * EE);
    reduce4_br_kernel<<<(PP * EE) / 256, 256>>>(split, pa_out_b, nullptr, patcho, EE, PP * EE);

    // 5) project to D + ppos: split-K x4 (K=512, 768 CTAs)
    gemm64_ks(patcho, proj_w, split,
              PP, DD, EE/4, EE, EE, DD,
              0, 0, 0, 1, 4, EE/4, EE/4, (long long)PP * DD);
    reduce4_br_kernel<<<(PP * DD) / 256, 256>>>(split, proj_b, ppos, h, DD, PP * DD);

    const float tr_scale = 0.1020620726159657588f;   // 1/sqrt(96)

    // LN1 of layer 0
    ln_kernel<<<PP, 256>>>(h, ln1w, ln1b, hn);

    for (int i = 0; i < NLAY; i++) {
        const float* qkv_w = lw_qkv + (size_t)i * 3 * DD * DD;
        const float* qkv_b = lb_qkv + (size_t)i * 3 * DD;
        const float* out_w = lw_out + (size_t)i * DD * DD;
        const float* out_b = lb_out + (size_t)i * DD;
        const float* f1w   = ffw1  + (size_t)i * FFD * DD;
        const float* f1b   = ffb1  + (size_t)i * FFD;
        const float* f2w   = ffw2  + (size_t)i * DD * FFD;
        const float* f2b   = ffb2  + (size_t)i * DD;

        // QKV (hn holds LN1 output)
        gemm64(hn, qkv_w, qkv_b, nullptr, qkvt,
               PP, 3*DD, DD, DD, DD, 3*DD, 0, 0, 0, 1, 1);
        // transpose V (coalesced smem-tile transpose)
        transpose_v_kernel<<<dim3(PP/32, DD/32), 256>>>(qkvt, vt);
        // scores per head (batched over 8 heads)
        gemm128(qkvt, qkvt + DD, nullptr, nullptr, scores,
                PP, PP, 96, 3*DD, 3*DD, PP,
                96, 96, (long long)PP * PP, 8, 0);
        softmax_kernel<<<8 * PP, 256>>>(scores, tr_scale);
        // AV split-K x4: 8 heads x 4 k-chunks of 256 -> 1024 CTAs
        gemm64_ks(scores, vt, split,
                  PP, 96, PP/4, PP, PP, DD,
                  (long long)PP * PP, (long long)96 * PP, 96, 8, 4,
                  PP/4, PP/4, (long long)PP * DD);
        reduce4_kernel<<<(PP * DD) / 256, 256>>>(split, attnt);
        // out-proj split-K x4 (bias+residual+LN2 in reduce)
        gemm64_ks(attnt, out_w, split,
                  PP, DD, DD/4, DD, DD, DD,
                  0, 0, 0, 1, 4,
                  DD/4, DD/4, (long long)PP * DD);
        reduce4_ln_kernel<<<PP, 256>>>(split, out_b, h,
                                       ln2w + (size_t)i * DD, ln2b + (size_t)i * DD, hn);
        // FF1 + gelu
        gemm64(hn, f1w, f1b, nullptr, ff,
               PP, FFD, DD, DD, DD, FFD, 0, 0, 0, 1, 2);
        // FF2 split-K x4
        gemm64_ks(ff, f2w, split,
                  PP, DD, FFD/4, FFD, FFD, DD,
                  0, 0, 0, 1, 4,
                  FFD/4, FFD/4, (long long)PP * DD);
        // fused reduce + residual + next LN
        if (i + 1 < NLAY) {
            reduce4_ln_kernel<<<PP, 256>>>(split, f2b, h,
                                           ln1w + (size_t)(i+1) * DD, ln1b + (size_t)(i+1) * DD, hn);
        } else {
            reduce4_ln_kernel<<<PP, 256>>>(split, f2b, h, lnfw, lnfb, out);
        }
    }
}